// round 16
// baseline (speedup 1.0000x reference)
#include <cuda_runtime.h>

// Problem constants (fixed by setup_inputs)
#define OBS   128
#define ACTD  32
#define HID   512
#define BB    32
#define TT    64
#define NNA   64
#define HOR   63
#define KC    16
#define NCHUNK 42            // 672 / 16 : 32 h-chunks + 8 obs + 2 act
#define INDIM (OBS + ACTD)   // 160

typedef unsigned long long u64;

__device__ __forceinline__ u64 pack2(float x, float y) {
    u64 r; asm("mov.b64 %0, {%1,%2};" : "=l"(r) : "f"(x), "f"(y)); return r;
}
__device__ __forceinline__ void unpack2(u64 v, float &x, float &y) {
    float a, b; asm("mov.b64 {%0,%1}, %2;" : "=f"(a), "=f"(b) : "l"(v)); x = a; y = b;
}
__device__ __forceinline__ void fma2(u64 &c, u64 a, u64 b) {
    asm("fma.rn.f32x2 %0, %1, %2, %0;" : "+l"(c) : "l"(a), "l"(b));
}
__device__ __forceinline__ float sigmoidf_(float x) {
    return 1.f / (1.f + __expf(-x));
}
__device__ __forceinline__ float tanhf_(float x) {
    float e = __expf(2.f * x);
    return 1.f - 2.f / (e + 1.f);   // saturates correctly at +-1 for |x| large
}

// ---------------------------------------------------------------------------
// Per-step fused GRU kernel.
// Output tile 64(M) x 64(j), 256 threads, 4x4 outputs per thread.
// Four accumulator groups per output (r, z, n_x, n_h); per k-chunk only 3 are
// active (h-phase: r,z,n_h ; x-phase: r,z,n_x).
// h state lives in the hs slice of d_out: hs[b, s, n, :].
// ---------------------------------------------------------------------------
__global__ void __launch_bounds__(256, 2)
gru_step_kernel(const float* __restrict__ obs, const float* __restrict__ act,
                const float* __restrict__ w_ih, const float* __restrict__ w_hh,
                const float* __restrict__ b_ih, const float* __restrict__ b_hh,
                float* __restrict__ hs, int s)
{
    __shared__ __align__(16) float As[2][KC][64];
    __shared__ __align__(16) float Bs[2][3][KC][64];

    const int tid = threadIdx.x;
    const int m0  = blockIdx.y * 64;
    const int j0  = blockIdx.x * 64;

    // loader mapping: one float4 per source per thread
    const int lm  = tid >> 2;          // 0..63 (row m within tile for A / col j for B)
    const int lk4 = (tid & 3) << 2;    // k offset within chunk

    const int gm = m0 + lm;
    const int gb = gm >> 6;
    const int gn = gm & 63;

    const float* obs_row = obs + (((size_t)gb * TT + s) * NNA + gn) * OBS;
    const float* act_row = act + (((size_t)gb * TT + s) * NNA + gn) * ACTD;
    const float* hp_row  = hs  + (((size_t)gb * HOR + (s > 0 ? s - 1 : 0)) * NNA + gn) * HID;

    const int bj = j0 + lm;            // global output column for B loads

    // compute mapping
    const int tm0 = (tid & 15) << 2;   // 16 x 4 = 64 rows
    const int tn0 = (tid >> 4) << 2;   // 16 x 4 = 64 cols

    u64 aR[4][2], aZ[4][2], aNX[4][2], aNH[4][2];
#pragma unroll
    for (int i = 0; i < 4; i++) {
        aR[i][0] = aR[i][1] = 0ULL; aZ[i][0] = aZ[i][1] = 0ULL;
        aNX[i][0] = aNX[i][1] = 0ULL; aNH[i][0] = aNH[i][1] = 0ULL;
    }

    float4 ar, b0r, b1r, b2r;

#define LOAD_CHUNK(c) do {                                                              \
    int k0_ = (c) * KC;                                                                 \
    int k_  = k0_ + lk4;                                                                \
    if (k0_ < HID) {                                                                    \
        ar = (s > 0) ? *reinterpret_cast<const float4*>(hp_row + k_)                    \
                     : make_float4(0.f, 0.f, 0.f, 0.f);                                 \
        const float* wp_ = w_hh + k_;                                                   \
        b0r = *reinterpret_cast<const float4*>(wp_ + (size_t)bj * HID);                 \
        b1r = *reinterpret_cast<const float4*>(wp_ + (size_t)(bj + HID) * HID);         \
        b2r = *reinterpret_cast<const float4*>(wp_ + (size_t)(bj + 2 * HID) * HID);     \
    } else {                                                                            \
        int kk_ = k_ - HID;                                                             \
        ar = (kk_ < OBS) ? *reinterpret_cast<const float4*>(obs_row + kk_)              \
                         : *reinterpret_cast<const float4*>(act_row + kk_ - OBS);       \
        const float* wp_ = w_ih + kk_;                                                  \
        b0r = *reinterpret_cast<const float4*>(wp_ + (size_t)bj * INDIM);               \
        b1r = *reinterpret_cast<const float4*>(wp_ + (size_t)(bj + HID) * INDIM);       \
        b2r = *reinterpret_cast<const float4*>(wp_ + (size_t)(bj + 2 * HID) * INDIM);   \
    }                                                                                   \
} while (0)

#define STORE_CHUNK(bf) do {                                                            \
    As[bf][lk4 + 0][lm] = ar.x; As[bf][lk4 + 1][lm] = ar.y;                             \
    As[bf][lk4 + 2][lm] = ar.z; As[bf][lk4 + 3][lm] = ar.w;                             \
    Bs[bf][0][lk4 + 0][lm] = b0r.x; Bs[bf][0][lk4 + 1][lm] = b0r.y;                     \
    Bs[bf][0][lk4 + 2][lm] = b0r.z; Bs[bf][0][lk4 + 3][lm] = b0r.w;                     \
    Bs[bf][1][lk4 + 0][lm] = b1r.x; Bs[bf][1][lk4 + 1][lm] = b1r.y;                     \
    Bs[bf][1][lk4 + 2][lm] = b1r.z; Bs[bf][1][lk4 + 3][lm] = b1r.w;                     \
    Bs[bf][2][lk4 + 0][lm] = b2r.x; Bs[bf][2][lk4 + 1][lm] = b2r.y;                     \
    Bs[bf][2][lk4 + 2][lm] = b2r.z; Bs[bf][2][lk4 + 3][lm] = b2r.w;                     \
} while (0)

#define INNER(bf, ACC3) do {                                                            \
    _Pragma("unroll")                                                                   \
    for (int k = 0; k < KC; k++) {                                                      \
        float4 av = *reinterpret_cast<const float4*>(&As[bf][k][tm0]);                  \
        u64 a_[4];                                                                      \
        a_[0] = pack2(av.x, av.x); a_[1] = pack2(av.y, av.y);                           \
        a_[2] = pack2(av.z, av.z); a_[3] = pack2(av.w, av.w);                           \
        ulonglong2 b0_ = *reinterpret_cast<const ulonglong2*>(&Bs[bf][0][k][tn0]);      \
        ulonglong2 b1_ = *reinterpret_cast<const ulonglong2*>(&Bs[bf][1][k][tn0]);      \
        ulonglong2 b2_ = *reinterpret_cast<const ulonglong2*>(&Bs[bf][2][k][tn0]);      \
        _Pragma("unroll")                                                               \
        for (int i = 0; i < 4; i++) {                                                   \
            fma2(aR[i][0],   a_[i], b0_.x); fma2(aR[i][1],   a_[i], b0_.y);             \
            fma2(aZ[i][0],   a_[i], b1_.x); fma2(aZ[i][1],   a_[i], b1_.y);             \
            fma2(ACC3[i][0], a_[i], b2_.x); fma2(ACC3[i][1], a_[i], b2_.y);             \
        }                                                                               \
    }                                                                                   \
} while (0)

    const int c0 = (s > 0) ? 0 : 32;   // h is zero at step 0: skip all h-chunks
    LOAD_CHUNK(c0);
    int buf = 0;
#pragma unroll 1
    for (int c = c0; c < NCHUNK; ++c) {
        STORE_CHUNK(buf);
        __syncthreads();               // single barrier per chunk (double buffered)
        if (c + 1 < NCHUNK) LOAD_CHUNK(c + 1);
        if (c < 32) { INNER(buf, aNH); } else { INNER(buf, aNX); }
        buf ^= 1;
    }

    // ---- epilogue: gates + state update, write h_new into hs[b, s, n, :] ----
    const int jt = j0 + tn0;
    float cr[4], cz[4], bin_[4], bhn_[4];
#pragma unroll
    for (int jj = 0; jj < 4; jj++) {
        cr[jj]   = b_ih[jt + jj]            + b_hh[jt + jj];
        cz[jj]   = b_ih[HID + jt + jj]      + b_hh[HID + jt + jj];
        bin_[jj] = b_ih[2 * HID + jt + jj];
        bhn_[jj] = b_hh[2 * HID + jt + jj];
    }
#pragma unroll
    for (int i = 0; i < 4; i++) {
        int m = m0 + tm0 + i;
        int b = m >> 6, n = m & 63;
        float* orow       = hs + (((size_t)b * HOR + s) * NNA + n) * HID + jt;
        const float* prow = hs + (((size_t)b * HOR + (s > 0 ? s - 1 : 0)) * NNA + n) * HID + jt;
        float4 hp = (s > 0) ? *reinterpret_cast<const float4*>(prow)
                            : make_float4(0.f, 0.f, 0.f, 0.f);
        float hpv[4] = {hp.x, hp.y, hp.z, hp.w};
        float sr[4], sz[4], sx[4], sh[4];
        unpack2(aR[i][0],  sr[0], sr[1]); unpack2(aR[i][1],  sr[2], sr[3]);
        unpack2(aZ[i][0],  sz[0], sz[1]); unpack2(aZ[i][1],  sz[2], sz[3]);
        unpack2(aNX[i][0], sx[0], sx[1]); unpack2(aNX[i][1], sx[2], sx[3]);
        unpack2(aNH[i][0], sh[0], sh[1]); unpack2(aNH[i][1], sh[2], sh[3]);
        float out[4];
#pragma unroll
        for (int jj = 0; jj < 4; jj++) {
            float r  = sigmoidf_(sr[jj] + cr[jj]);
            float z  = sigmoidf_(sz[jj] + cz[jj]);
            float nv = tanhf_(sx[jj] + bin_[jj] + r * (sh[jj] + bhn_[jj]));
            out[jj] = (1.f - z) * nv + z * hpv[jj];
        }
        *reinterpret_cast<float4*>(orow) = make_float4(out[0], out[1], out[2], out[3]);
    }
#undef LOAD_CHUNK
#undef STORE_CHUNK
#undef INNER
}

// ---------------------------------------------------------------------------
// Batched decoder: preds = hs_all @ w_dec^T + b_dec
// M = 129024, N = 128, K = 512.  Tile 128 x 64, 256 threads, 8x4 per thread.
// ---------------------------------------------------------------------------
__global__ void __launch_bounds__(256, 2)
dec_kernel(const float* __restrict__ hs, const float* __restrict__ w_dec,
           const float* __restrict__ b_dec, float* __restrict__ preds)
{
    __shared__ __align__(16) float As[2][KC][128];
    __shared__ __align__(16) float Bs[2][KC][64];

    const int tid = threadIdx.x;
    const int r0  = blockIdx.y * 128;
    const int j0  = blockIdx.x * 64;

    const int lm  = tid >> 2;          // 0..63
    const int lk4 = (tid & 3) << 2;

    const float* a0p = hs + (size_t)(r0 + lm) * HID + lk4;
    const float* a1p = hs + (size_t)(r0 + lm + 64) * HID + lk4;
    const float* bp  = w_dec + (size_t)(j0 + lm) * HID + lk4;

    const int tm0 = (tid & 15) << 3;   // 16 x 8 = 128 rows
    const int tn0 = (tid >> 4) << 2;   // 16 x 4 = 64 cols

    u64 acc[8][2];
#pragma unroll
    for (int i = 0; i < 8; i++) { acc[i][0] = 0ULL; acc[i][1] = 0ULL; }

    float4 ar0 = *reinterpret_cast<const float4*>(a0p);
    float4 ar1 = *reinterpret_cast<const float4*>(a1p);
    float4 br  = *reinterpret_cast<const float4*>(bp);

    int buf = 0;
#pragma unroll 1
    for (int c = 0; c < HID / KC; ++c) {
        As[buf][lk4 + 0][lm] = ar0.x; As[buf][lk4 + 1][lm] = ar0.y;
        As[buf][lk4 + 2][lm] = ar0.z; As[buf][lk4 + 3][lm] = ar0.w;
        As[buf][lk4 + 0][lm + 64] = ar1.x; As[buf][lk4 + 1][lm + 64] = ar1.y;
        As[buf][lk4 + 2][lm + 64] = ar1.z; As[buf][lk4 + 3][lm + 64] = ar1.w;
        Bs[buf][lk4 + 0][lm] = br.x; Bs[buf][lk4 + 1][lm] = br.y;
        Bs[buf][lk4 + 2][lm] = br.z; Bs[buf][lk4 + 3][lm] = br.w;
        __syncthreads();
        if (c + 1 < HID / KC) {
            int off = (c + 1) * KC;
            ar0 = *reinterpret_cast<const float4*>(a0p + off);
            ar1 = *reinterpret_cast<const float4*>(a1p + off);
            br  = *reinterpret_cast<const float4*>(bp + off);
        }
#pragma unroll
        for (int k = 0; k < KC; k++) {
            float4 av0 = *reinterpret_cast<const float4*>(&As[buf][k][tm0]);
            float4 av1 = *reinterpret_cast<const float4*>(&As[buf][k][tm0 + 4]);
            ulonglong2 bv = *reinterpret_cast<const ulonglong2*>(&Bs[buf][k][tn0]);
            u64 a_[8];
            a_[0] = pack2(av0.x, av0.x); a_[1] = pack2(av0.y, av0.y);
            a_[2] = pack2(av0.z, av0.z); a_[3] = pack2(av0.w, av0.w);
            a_[4] = pack2(av1.x, av1.x); a_[5] = pack2(av1.y, av1.y);
            a_[6] = pack2(av1.z, av1.z); a_[7] = pack2(av1.w, av1.w);
#pragma unroll
            for (int i = 0; i < 8; i++) {
                fma2(acc[i][0], a_[i], bv.x);
                fma2(acc[i][1], a_[i], bv.y);
            }
        }
        buf ^= 1;
    }

    const int jt = j0 + tn0;
    float bd0 = b_dec[jt], bd1 = b_dec[jt + 1], bd2 = b_dec[jt + 2], bd3 = b_dec[jt + 3];
#pragma unroll
    for (int i = 0; i < 8; i++) {
        float s0, s1, s2, s3;
        unpack2(acc[i][0], s0, s1); unpack2(acc[i][1], s2, s3);
        size_t row = (size_t)(r0 + tm0 + i) * OBS;
        *reinterpret_cast<float4*>(preds + row + jt) =
            make_float4(s0 + bd0, s1 + bd1, s2 + bd2, s3 + bd3);
    }
}

// ---------------------------------------------------------------------------
extern "C" void kernel_launch(void* const* d_in, const int* in_sizes, int n_in,
                              void* d_out, int out_size)
{
    (void)in_sizes; (void)n_in; (void)out_size;
    const float* obs   = (const float*)d_in[0];
    const float* act   = (const float*)d_in[1];
    const float* w_ih  = (const float*)d_in[2];
    const float* w_hh  = (const float*)d_in[3];
    const float* b_ih  = (const float*)d_in[4];
    const float* b_hh  = (const float*)d_in[5];
    const float* w_dec = (const float*)d_in[6];
    const float* b_dec = (const float*)d_in[7];
    // horizon (d_in[8]) is fixed at 63 by the problem setup

    float* preds = (float*)d_out;
    float* hs    = preds + (size_t)BB * HOR * NNA * OBS;   // hs follows preds

    dim3 gstep(HID / 64, (BB * NNA) / 64);   // 8 x 32 CTAs
    for (int s = 0; s < HOR; ++s) {
        gru_step_kernel<<<gstep, 256>>>(obs, act, w_ih, w_hh, b_ih, b_hh, hs, s);
    }

    dim3 gdec(OBS / 64, (BB * HOR * NNA) / 128);  // 2 x 1008 CTAs
    dec_kernel<<<gdec, 256>>>(hs, w_dec, b_dec, preds);
}

// round 17
// speedup vs baseline: 1.0009x; 1.0009x over previous
#include <cuda_runtime.h>

// Problem constants (fixed by setup_inputs)
#define OBS   128
#define ACTD  32
#define HID   512
#define BB    32
#define TT    64
#define NNA   64
#define HOR   63
#define KC    16
#define NCHUNK 42            // 672 / 16 : 32 h-chunks + 8 obs + 2 act
#define INDIM (OBS + ACTD)   // 160

typedef unsigned long long u64;

__device__ __forceinline__ u64 pack2(float x, float y) {
    u64 r; asm("mov.b64 %0, {%1,%2};" : "=l"(r) : "f"(x), "f"(y)); return r;
}
__device__ __forceinline__ void unpack2(u64 v, float &x, float &y) {
    float a, b; asm("mov.b64 {%0,%1}, %2;" : "=f"(a), "=f"(b) : "l"(v)); x = a; y = b;
}
__device__ __forceinline__ void fma2(u64 &c, u64 a, u64 b) {
    asm("fma.rn.f32x2 %0, %1, %2, %0;" : "+l"(c) : "l"(a), "l"(b));
}
__device__ __forceinline__ float sigmoidf_(float x) {
    return 1.f / (1.f + __expf(-x));
}
__device__ __forceinline__ float tanhf_(float x) {
    float e = __expf(2.f * x);
    return 1.f - 2.f / (e + 1.f);   // saturates correctly at +-1 for |x| large
}

// ---------------------------------------------------------------------------
// Per-step fused GRU kernel.
// Output tile 64(M) x 64(j), 256 threads, 4x4 outputs per thread.
// Four accumulator groups per output (r, z, n_x, n_h); per k-chunk only 3 are
// active (h-phase: r,z,n_h ; x-phase: r,z,n_x).
// h state lives in the hs slice of d_out: hs[b, s, n, :].
// ---------------------------------------------------------------------------
__global__ void __launch_bounds__(256, 2)
gru_step_kernel(const float* __restrict__ obs, const float* __restrict__ act,
                const float* __restrict__ w_ih, const float* __restrict__ w_hh,
                const float* __restrict__ b_ih, const float* __restrict__ b_hh,
                float* __restrict__ hs, int s)
{
    __shared__ __align__(16) float As[2][KC][64];
    __shared__ __align__(16) float Bs[2][3][KC][64];

    const int tid = threadIdx.x;
    const int m0  = blockIdx.y * 64;
    const int j0  = blockIdx.x * 64;

    // loader mapping: one float4 per source per thread
    const int lm  = tid >> 2;          // 0..63 (row m within tile for A / col j for B)
    const int lk4 = (tid & 3) << 2;    // k offset within chunk

    const int gm = m0 + lm;
    const int gb = gm >> 6;
    const int gn = gm & 63;

    const float* obs_row = obs + (((size_t)gb * TT + s) * NNA + gn) * OBS;
    const float* act_row = act + (((size_t)gb * TT + s) * NNA + gn) * ACTD;
    const float* hp_row  = hs  + (((size_t)gb * HOR + (s > 0 ? s - 1 : 0)) * NNA + gn) * HID;

    const int bj = j0 + lm;            // global output column for B loads

    // compute mapping
    const int tm0 = (tid & 15) << 2;   // 16 x 4 = 64 rows
    const int tn0 = (tid >> 4) << 2;   // 16 x 4 = 64 cols

    u64 aR[4][2], aZ[4][2], aNX[4][2], aNH[4][2];
#pragma unroll
    for (int i = 0; i < 4; i++) {
        aR[i][0] = aR[i][1] = 0ULL; aZ[i][0] = aZ[i][1] = 0ULL;
        aNX[i][0] = aNX[i][1] = 0ULL; aNH[i][0] = aNH[i][1] = 0ULL;
    }

    float4 ar, b0r, b1r, b2r;

#define LOAD_CHUNK(c) do {                                                              \
    int k0_ = (c) * KC;                                                                 \
    int k_  = k0_ + lk4;                                                                \
    if (k0_ < HID) {                                                                    \
        ar = (s > 0) ? *reinterpret_cast<const float4*>(hp_row + k_)                    \
                     : make_float4(0.f, 0.f, 0.f, 0.f);                                 \
        const float* wp_ = w_hh + k_;                                                   \
        b0r = *reinterpret_cast<const float4*>(wp_ + (size_t)bj * HID);                 \
        b1r = *reinterpret_cast<const float4*>(wp_ + (size_t)(bj + HID) * HID);         \
        b2r = *reinterpret_cast<const float4*>(wp_ + (size_t)(bj + 2 * HID) * HID);     \
    } else {                                                                            \
        int kk_ = k_ - HID;                                                             \
        ar = (kk_ < OBS) ? *reinterpret_cast<const float4*>(obs_row + kk_)              \
                         : *reinterpret_cast<const float4*>(act_row + kk_ - OBS);       \
        const float* wp_ = w_ih + kk_;                                                  \
        b0r = *reinterpret_cast<const float4*>(wp_ + (size_t)bj * INDIM);               \
        b1r = *reinterpret_cast<const float4*>(wp_ + (size_t)(bj + HID) * INDIM);       \
        b2r = *reinterpret_cast<const float4*>(wp_ + (size_t)(bj + 2 * HID) * INDIM);   \
    }                                                                                   \
} while (0)

#define STORE_CHUNK(bf) do {                                                            \
    As[bf][lk4 + 0][lm] = ar.x; As[bf][lk4 + 1][lm] = ar.y;                             \
    As[bf][lk4 + 2][lm] = ar.z; As[bf][lk4 + 3][lm] = ar.w;                             \
    Bs[bf][0][lk4 + 0][lm] = b0r.x; Bs[bf][0][lk4 + 1][lm] = b0r.y;                     \
    Bs[bf][0][lk4 + 2][lm] = b0r.z; Bs[bf][0][lk4 + 3][lm] = b0r.w;                     \
    Bs[bf][1][lk4 + 0][lm] = b1r.x; Bs[bf][1][lk4 + 1][lm] = b1r.y;                     \
    Bs[bf][1][lk4 + 2][lm] = b1r.z; Bs[bf][1][lk4 + 3][lm] = b1r.w;                     \
    Bs[bf][2][lk4 + 0][lm] = b2r.x; Bs[bf][2][lk4 + 1][lm] = b2r.y;                     \
    Bs[bf][2][lk4 + 2][lm] = b2r.z; Bs[bf][2][lk4 + 3][lm] = b2r.w;                     \
} while (0)

#define INNER(bf, ACC3) do {                                                            \
    _Pragma("unroll")                                                                   \
    for (int k = 0; k < KC; k++) {                                                      \
        float4 av = *reinterpret_cast<const float4*>(&As[bf][k][tm0]);                  \
        u64 a_[4];                                                                      \
        a_[0] = pack2(av.x, av.x); a_[1] = pack2(av.y, av.y);                           \
        a_[2] = pack2(av.z, av.z); a_[3] = pack2(av.w, av.w);                           \
        ulonglong2 b0_ = *reinterpret_cast<const ulonglong2*>(&Bs[bf][0][k][tn0]);      \
        ulonglong2 b1_ = *reinterpret_cast<const ulonglong2*>(&Bs[bf][1][k][tn0]);      \
        ulonglong2 b2_ = *reinterpret_cast<const ulonglong2*>(&Bs[bf][2][k][tn0]);      \
        _Pragma("unroll")                                                               \
        for (int i = 0; i < 4; i++) {                                                   \
            fma2(aR[i][0],   a_[i], b0_.x); fma2(aR[i][1],   a_[i], b0_.y);             \
            fma2(aZ[i][0],   a_[i], b1_.x); fma2(aZ[i][1],   a_[i], b1_.y);             \
            fma2(ACC3[i][0], a_[i], b2_.x); fma2(ACC3[i][1], a_[i], b2_.y);             \
        }                                                                               \
    }                                                                                   \
} while (0)

    const int c0 = (s > 0) ? 0 : 32;   // h is zero at step 0: skip all h-chunks
    LOAD_CHUNK(c0);
    int buf = 0;
#pragma unroll 1
    for (int c = c0; c < NCHUNK; ++c) {
        STORE_CHUNK(buf);
        __syncthreads();               // single barrier per chunk (double buffered)
        if (c + 1 < NCHUNK) LOAD_CHUNK(c + 1);
        if (c < 32) { INNER(buf, aNH); } else { INNER(buf, aNX); }
        buf ^= 1;
    }

    // ---- epilogue: gates + state update, write h_new into hs[b, s, n, :] ----
    const int jt = j0 + tn0;
    float cr[4], cz[4], bin_[4], bhn_[4];
#pragma unroll
    for (int jj = 0; jj < 4; jj++) {
        cr[jj]   = b_ih[jt + jj]            + b_hh[jt + jj];
        cz[jj]   = b_ih[HID + jt + jj]      + b_hh[HID + jt + jj];
        bin_[jj] = b_ih[2 * HID + jt + jj];
        bhn_[jj] = b_hh[2 * HID + jt + jj];
    }
#pragma unroll
    for (int i = 0; i < 4; i++) {
        int m = m0 + tm0 + i;
        int b = m >> 6, n = m & 63;
        float* orow       = hs + (((size_t)b * HOR + s) * NNA + n) * HID + jt;
        const float* prow = hs + (((size_t)b * HOR + (s > 0 ? s - 1 : 0)) * NNA + n) * HID + jt;
        float4 hp = (s > 0) ? *reinterpret_cast<const float4*>(prow)
                            : make_float4(0.f, 0.f, 0.f, 0.f);
        float hpv[4] = {hp.x, hp.y, hp.z, hp.w};
        float sr[4], sz[4], sx[4], sh[4];
        unpack2(aR[i][0],  sr[0], sr[1]); unpack2(aR[i][1],  sr[2], sr[3]);
        unpack2(aZ[i][0],  sz[0], sz[1]); unpack2(aZ[i][1],  sz[2], sz[3]);
        unpack2(aNX[i][0], sx[0], sx[1]); unpack2(aNX[i][1], sx[2], sx[3]);
        unpack2(aNH[i][0], sh[0], sh[1]); unpack2(aNH[i][1], sh[2], sh[3]);
        float out[4];
#pragma unroll
        for (int jj = 0; jj < 4; jj++) {
            float r  = sigmoidf_(sr[jj] + cr[jj]);
            float z  = sigmoidf_(sz[jj] + cz[jj]);
            float nv = tanhf_(sx[jj] + bin_[jj] + r * (sh[jj] + bhn_[jj]));
            out[jj] = (1.f - z) * nv + z * hpv[jj];
        }
        *reinterpret_cast<float4*>(orow) = make_float4(out[0], out[1], out[2], out[3]);
    }
#undef LOAD_CHUNK
#undef STORE_CHUNK
#undef INNER
}

// ---------------------------------------------------------------------------
// Batched decoder: preds = hs_all @ w_dec^T + b_dec
// M = 129024, N = 128, K = 512.  Tile 128 x 64, 256 threads, 8x4 per thread.
// ---------------------------------------------------------------------------
__global__ void __launch_bounds__(256, 2)
dec_kernel(const float* __restrict__ hs, const float* __restrict__ w_dec,
           const float* __restrict__ b_dec, float* __restrict__ preds)
{
    __shared__ __align__(16) float As[2][KC][128];
    __shared__ __align__(16) float Bs[2][KC][64];

    const int tid = threadIdx.x;
    const int r0  = blockIdx.y * 128;
    const int j0  = blockIdx.x * 64;

    const int lm  = tid >> 2;          // 0..63
    const int lk4 = (tid & 3) << 2;

    const float* a0p = hs + (size_t)(r0 + lm) * HID + lk4;
    const float* a1p = hs + (size_t)(r0 + lm + 64) * HID + lk4;
    const float* bp  = w_dec + (size_t)(j0 + lm) * HID + lk4;

    const int tm0 = (tid & 15) << 3;   // 16 x 8 = 128 rows
    const int tn0 = (tid >> 4) << 2;   // 16 x 4 = 64 cols

    u64 acc[8][2];
#pragma unroll
    for (int i = 0; i < 8; i++) { acc[i][0] = 0ULL; acc[i][1] = 0ULL; }

    float4 ar0 = *reinterpret_cast<const float4*>(a0p);
    float4 ar1 = *reinterpret_cast<const float4*>(a1p);
    float4 br  = *reinterpret_cast<const float4*>(bp);

    int buf = 0;
#pragma unroll 1
    for (int c = 0; c < HID / KC; ++c) {
        As[buf][lk4 + 0][lm] = ar0.x; As[buf][lk4 + 1][lm] = ar0.y;
        As[buf][lk4 + 2][lm] = ar0.z; As[buf][lk4 + 3][lm] = ar0.w;
        As[buf][lk4 + 0][lm + 64] = ar1.x; As[buf][lk4 + 1][lm + 64] = ar1.y;
        As[buf][lk4 + 2][lm + 64] = ar1.z; As[buf][lk4 + 3][lm + 64] = ar1.w;
        Bs[buf][lk4 + 0][lm] = br.x; Bs[buf][lk4 + 1][lm] = br.y;
        Bs[buf][lk4 + 2][lm] = br.z; Bs[buf][lk4 + 3][lm] = br.w;
        __syncthreads();
        if (c + 1 < HID / KC) {
            int off = (c + 1) * KC;
            ar0 = *reinterpret_cast<const float4*>(a0p + off);
            ar1 = *reinterpret_cast<const float4*>(a1p + off);
            br  = *reinterpret_cast<const float4*>(bp + off);
        }
#pragma unroll
        for (int k = 0; k < KC; k++) {
            float4 av0 = *reinterpret_cast<const float4*>(&As[buf][k][tm0]);
            float4 av1 = *reinterpret_cast<const float4*>(&As[buf][k][tm0 + 4]);
            ulonglong2 bv = *reinterpret_cast<const ulonglong2*>(&Bs[buf][k][tn0]);
            u64 a_[8];
            a_[0] = pack2(av0.x, av0.x); a_[1] = pack2(av0.y, av0.y);
            a_[2] = pack2(av0.z, av0.z); a_[3] = pack2(av0.w, av0.w);
            a_[4] = pack2(av1.x, av1.x); a_[5] = pack2(av1.y, av1.y);
            a_[6] = pack2(av1.z, av1.z); a_[7] = pack2(av1.w, av1.w);
#pragma unroll
            for (int i = 0; i < 8; i++) {
                fma2(acc[i][0], a_[i], bv.x);
                fma2(acc[i][1], a_[i], bv.y);
            }
        }
        buf ^= 1;
    }

    const int jt = j0 + tn0;
    float bd0 = b_dec[jt], bd1 = b_dec[jt + 1], bd2 = b_dec[jt + 2], bd3 = b_dec[jt + 3];
#pragma unroll
    for (int i = 0; i < 8; i++) {
        float s0, s1, s2, s3;
        unpack2(acc[i][0], s0, s1); unpack2(acc[i][1], s2, s3);
        size_t row = (size_t)(r0 + tm0 + i) * OBS;
        *reinterpret_cast<float4*>(preds + row + jt) =
            make_float4(s0 + bd0, s1 + bd1, s2 + bd2, s3 + bd3);
    }
}

// ---------------------------------------------------------------------------
extern "C" void kernel_launch(void* const* d_in, const int* in_sizes, int n_in,
                              void* d_out, int out_size)
{
    (void)in_sizes; (void)n_in; (void)out_size;
    const float* obs   = (const float*)d_in[0];
    const float* act   = (const float*)d_in[1];
    const float* w_ih  = (const float*)d_in[2];
    const float* w_hh  = (const float*)d_in[3];
    const float* b_ih  = (const float*)d_in[4];
    const float* b_hh  = (const float*)d_in[5];
    const float* w_dec = (const float*)d_in[6];
    const float* b_dec = (const float*)d_in[7];
    // horizon (d_in[8]) is fixed at 63 by the problem setup

    float* preds = (float*)d_out;
    float* hs    = preds + (size_t)BB * HOR * NNA * OBS;   // hs follows preds

    dim3 gstep(HID / 64, (BB * NNA) / 64);   // 8 x 32 CTAs
    for (int s = 0; s < HOR; ++s) {
        gru_step_kernel<<<gstep, 256>>>(obs, act, w_ih, w_hh, b_ih, b_hh, hs, s);
    }

    dim3 gdec(OBS / 64, (BB * HOR * NNA) / 128);  // 2 x 1008 CTAs
    dec_kernel<<<gdec, 256>>>(hs, w_dec, b_dec, preds);
}